// round 2
// baseline (speedup 1.0000x reference)
#include <cuda_runtime.h>
#include <cstdint>

// SparseProjection: out[b,k] = dot(weight[indices[b,k]], inp[b]) + bias[indices[b,k]]
// B=4096, K=128, D=512, V=128000.  Inputs (metadata order):
//   d_in[0] inp     float32 [B, D]
//   d_in[1] indices [B, K]  -- dtype ambiguous (int64 in reference, harness may store int32)
//   d_in[2] sparse  scalar (always 1 -> sparse path)
//   d_in[3] weight  float32 [V, D]
//   d_in[4] bias    float32 [V]
// output: float32 [B, K]

#define D_DIM 512
#define K_DIM 128
#define D4 (D_DIM / 4)      // 128 float4 per row
#define THREADS 256         // 8 warps
#define WARPS (THREADS / 32)
#define K_PER_WARP (K_DIM / WARPS)  // 16

// 1 if indices buffer is int64, 0 if int32. Set by probe kernel each launch.
__device__ int g_idx_is64;

__global__ void probe_idx_dtype(const long long* __restrict__ idx64,
                                long long n_elems, long long vocab)
{
    // Interpret the first few entries as int64. If the buffer actually holds
    // int32 data, the int64 view packs two random indices per word and the
    // high 32 bits are nonzero with overwhelming probability.
    int ok = 1;
    long long n = n_elems < 256 ? n_elems : 256;
    for (long long i = 0; i < n; i++) {
        long long v = idx64[i];
        if (v < 0 || v >= vocab) { ok = 0; break; }
    }
    g_idx_is64 = ok;
}

__device__ __forceinline__ long long load_index(const void* idx, size_t i,
                                                int is64, long long vocab)
{
    long long v = is64 ? ((const long long*)idx)[i]
                       : (long long)((const int*)idx)[i];
    // Defensive clamp: wrong dtype guess degrades to wrong values, not a crash.
    v = v < 0 ? 0 : v;
    v = v >= vocab ? vocab - 1 : v;
    return v;
}

__global__ __launch_bounds__(THREADS)
void sparse_proj_kernel(const float4* __restrict__ inp,
                        const void* __restrict__ indices,
                        const float4* __restrict__ weight,
                        const float* __restrict__ bias,
                        float* __restrict__ out,
                        long long vocab)
{
    __shared__ float4 s_in[D4];

    const int b = blockIdx.x;
    const int tid = threadIdx.x;
    const int warp = tid >> 5;
    const int lane = tid & 31;
    const int is64 = g_idx_is64;

    // Stage inp[b] (2 KB) into shared memory: 128 float4, first 128 threads.
    if (tid < D4) {
        s_in[tid] = inp[(size_t)b * D4 + tid];
    }
    __syncthreads();

    // Preload this lane's 4 input float4s into registers (reused for all 16 k's).
    float4 iv0 = s_in[lane +  0];
    float4 iv1 = s_in[lane + 32];
    float4 iv2 = s_in[lane + 64];
    float4 iv3 = s_in[lane + 96];

    const size_t idx_base = (size_t)b * K_DIM + (size_t)warp * K_PER_WARP;
    float* out_row = out + idx_base;

    // Process 2 k's per iteration for load-level parallelism (8 independent
    // LDG.128 in flight per lane per iteration).
    #pragma unroll
    for (int kk = 0; kk < K_PER_WARP; kk += 2) {
        long long r0 = load_index(indices, idx_base + kk + 0, is64, vocab);
        long long r1 = load_index(indices, idx_base + kk + 1, is64, vocab);
        const float4* w0 = weight + r0 * D4;
        const float4* w1 = weight + r1 * D4;

        float4 a0 = w0[lane +  0];
        float4 a1 = w0[lane + 32];
        float4 a2 = w0[lane + 64];
        float4 a3 = w0[lane + 96];
        float4 b0 = w1[lane +  0];
        float4 b1 = w1[lane + 32];
        float4 b2 = w1[lane + 64];
        float4 b3 = w1[lane + 96];

        float acc0 = a0.x * iv0.x + a0.y * iv0.y + a0.z * iv0.z + a0.w * iv0.w;
        acc0      += a1.x * iv1.x + a1.y * iv1.y + a1.z * iv1.z + a1.w * iv1.w;
        acc0      += a2.x * iv2.x + a2.y * iv2.y + a2.z * iv2.z + a2.w * iv2.w;
        acc0      += a3.x * iv3.x + a3.y * iv3.y + a3.z * iv3.z + a3.w * iv3.w;

        float acc1 = b0.x * iv0.x + b0.y * iv0.y + b0.z * iv0.z + b0.w * iv0.w;
        acc1      += b1.x * iv1.x + b1.y * iv1.y + b1.z * iv1.z + b1.w * iv1.w;
        acc1      += b2.x * iv2.x + b2.y * iv2.y + b2.z * iv2.z + b2.w * iv2.w;
        acc1      += b3.x * iv3.x + b3.y * iv3.y + b3.z * iv3.z + b3.w * iv3.w;

        // Warp butterfly reduction (reduce both accumulators together).
        #pragma unroll
        for (int off = 16; off > 0; off >>= 1) {
            acc0 += __shfl_xor_sync(0xFFFFFFFFu, acc0, off);
            acc1 += __shfl_xor_sync(0xFFFFFFFFu, acc1, off);
        }

        if (lane == 0) {
            out_row[kk + 0] = acc0 + __ldg(bias + r0);
            out_row[kk + 1] = acc1 + __ldg(bias + r1);
        }
    }
}

extern "C" void kernel_launch(void* const* d_in, const int* in_sizes, int n_in,
                              void* d_out, int out_size)
{
    const float4* inp     = (const float4*)d_in[0];
    const void*   indices = d_in[1];
    // d_in[2] = sparse flag (always 1 for this dataset; sparse path implemented)
    const float4* weight  = (const float4*)d_in[3];
    const float*  bias    = (const float*)d_in[4];
    float*        out     = (float*)d_out;

    const int       B       = in_sizes[0] / D_DIM;       // 4096
    const long long n_idx   = (long long)in_sizes[1];    // B*K
    const long long vocab   = (long long)in_sizes[4];    // V = 128000

    probe_idx_dtype<<<1, 1>>>((const long long*)indices, n_idx, vocab);
    sparse_proj_kernel<<<B, THREADS>>>(inp, indices, weight, bias, out, vocab);
}

// round 3
// speedup vs baseline: 1.6207x; 1.6207x over previous
#include <cuda_runtime.h>
#include <cuda_fp16.h>
#include <cstdint>

// SparseProjection: out[b,k] = dot(weight[indices[b,k]], inp[b]) + bias[indices[b,k]]
// B=4096, K=128, D=512, V=128000.
// Strategy (CSR regroup): sort entries by vocab index; one warp per vocab row
// reads weight[v] ONCE (sequential DRAM stream) and loops over its ~4 entries,
// reading inp[b] (converted to fp16, 4MB, fully L2-resident).

#define D_DIM 512
#define D4 (D_DIM / 4)
#define B_FIXED 4096
#define K_FIXED 128
#define V_FIXED 128000
#define BK_FIXED (B_FIXED * K_FIXED)
#define SCAN_BLK 1024

// ---- static device scratch (no allocation allowed) ----
__device__ int    g_idx_is64;
__device__ int    g_counts[V_FIXED];
__device__ int    g_offsets[V_FIXED];
__device__ int    g_cursor[V_FIXED];
__device__ int    g_sorted[BK_FIXED];
__device__ int    g_partials[(V_FIXED + SCAN_BLK - 1) / SCAN_BLK + 1];
__device__ __half g_inp_h[B_FIXED * D_DIM];   // 4 MB fp16 copy of inp

// ---------------- dtype probe (indices may be int32 or int64) --------------
__global__ void probe_idx_dtype(const long long* __restrict__ idx64,
                                long long n_elems, long long vocab)
{
    int ok = 1;
    long long n = n_elems < 256 ? n_elems : 256;
    for (long long i = 0; i < n; i++) {
        long long v = idx64[i];
        if (v < 0 || v >= vocab) { ok = 0; break; }
    }
    g_idx_is64 = ok;
}

__device__ __forceinline__ long long load_index(const void* idx, size_t i,
                                                int is64, long long vocab)
{
    long long v = is64 ? ((const long long*)idx)[i]
                       : (long long)((const int*)idx)[i];
    v = v < 0 ? 0 : v;
    v = v >= vocab ? vocab - 1 : v;
    return v;
}

// ---------------- CSR build ----------------
__global__ void zero_counts(int V)
{
    int i = blockIdx.x * blockDim.x + threadIdx.x;
    if (i < V) g_counts[i] = 0;
}

__global__ void convert_inp_fp16(const float4* __restrict__ inp, int n4)
{
    int i = blockIdx.x * blockDim.x + threadIdx.x;
    if (i < n4) {
        float4 f = inp[i];
        __half2 lo = __floats2half2_rn(f.x, f.y);
        __half2 hi = __floats2half2_rn(f.z, f.w);
        uint2 p;
        p.x = *(const unsigned int*)&lo;
        p.y = *(const unsigned int*)&hi;
        ((uint2*)g_inp_h)[i] = p;
    }
}

__global__ void histogram_idx(const void* __restrict__ idx, int BK, long long vocab)
{
    int e = blockIdx.x * blockDim.x + threadIdx.x;
    if (e < BK) {
        long long v = load_index(idx, (size_t)e, g_idx_is64, vocab);
        atomicAdd(&g_counts[(int)v], 1);
    }
}

__global__ void scan_blocks(int V)
{
    __shared__ int s[SCAN_BLK];
    int i = blockIdx.x * SCAN_BLK + threadIdx.x;
    int x = (i < V) ? g_counts[i] : 0;
    s[threadIdx.x] = x;
    __syncthreads();
    #pragma unroll
    for (int off = 1; off < SCAN_BLK; off <<= 1) {
        int t = (threadIdx.x >= off) ? s[threadIdx.x - off] : 0;
        __syncthreads();
        s[threadIdx.x] += t;
        __syncthreads();
    }
    if (i < V) g_offsets[i] = s[threadIdx.x] - x;   // exclusive within block
    if (threadIdx.x == SCAN_BLK - 1) g_partials[blockIdx.x] = s[SCAN_BLK - 1];
}

__global__ void scan_partials(int nblk)
{
    int run = 0;
    for (int i = 0; i < nblk; i++) {
        int c = g_partials[i];
        g_partials[i] = run;
        run += c;
    }
}

__global__ void add_partials(int V)
{
    int i = blockIdx.x * SCAN_BLK + threadIdx.x;
    if (i < V) {
        int o = g_offsets[i] + g_partials[blockIdx.x];
        g_offsets[i] = o;
        g_cursor[i]  = o;
    }
}

__global__ void scatter_entries(const void* __restrict__ idx, int BK, long long vocab)
{
    int e = blockIdx.x * blockDim.x + threadIdx.x;
    if (e < BK) {
        long long v = load_index(idx, (size_t)e, g_idx_is64, vocab);
        int pos = atomicAdd(&g_cursor[(int)v], 1);
        g_sorted[pos] = e;
    }
}

// ---------------- main CSR kernel: one warp per vocab row ----------------
__device__ __forceinline__ float dot_w_h(float4 w, uint2 p)
{
    float2 lo = __half22float2(*(const __half2*)&p.x);
    float2 hi = __half22float2(*(const __half2*)&p.y);
    return w.x * lo.x + w.y * lo.y + w.z * hi.x + w.w * hi.y;
}

__global__ __launch_bounds__(256)
void csr_main(const float4* __restrict__ weight,
              const float*  __restrict__ bias,
              float* __restrict__ out,
              int V, int BK, int K)
{
    const int warp = threadIdx.x >> 5;
    const int lane = threadIdx.x & 31;
    const int v = blockIdx.x * 8 + warp;
    if (v >= V) return;

    const int start = g_offsets[v];
    const int end   = (v + 1 < V) ? g_offsets[v + 1] : BK;
    if (start >= end) return;

    const float4* wr = weight + (size_t)v * D4;
    float4 w0 = wr[lane +  0];
    float4 w1 = wr[lane + 32];
    float4 w2 = wr[lane + 64];
    float4 w3 = wr[lane + 96];
    const float bv = __ldg(bias + v);

    int i = start;
    for (; i + 2 <= end; i += 2) {
        int e0 = g_sorted[i];
        int e1 = g_sorted[i + 1];
        int b0 = e0 / K;
        int b1 = e1 / K;
        const uint2* r0 = (const uint2*)(g_inp_h + (size_t)b0 * D_DIM);
        const uint2* r1 = (const uint2*)(g_inp_h + (size_t)b1 * D_DIM);
        uint2 a0 = r0[lane +  0];
        uint2 a1 = r0[lane + 32];
        uint2 a2 = r0[lane + 64];
        uint2 a3 = r0[lane + 96];
        uint2 c0 = r1[lane +  0];
        uint2 c1 = r1[lane + 32];
        uint2 c2 = r1[lane + 64];
        uint2 c3 = r1[lane + 96];

        float acc0 = dot_w_h(w0, a0) + dot_w_h(w1, a1)
                   + dot_w_h(w2, a2) + dot_w_h(w3, a3);
        float acc1 = dot_w_h(w0, c0) + dot_w_h(w1, c1)
                   + dot_w_h(w2, c2) + dot_w_h(w3, c3);

        #pragma unroll
        for (int off = 16; off > 0; off >>= 1) {
            acc0 += __shfl_xor_sync(0xFFFFFFFFu, acc0, off);
            acc1 += __shfl_xor_sync(0xFFFFFFFFu, acc1, off);
        }
        if (lane == 0) {
            out[e0] = acc0 + bv;
            out[e1] = acc1 + bv;
        }
    }
    if (i < end) {
        int e0 = g_sorted[i];
        int b0 = e0 / K;
        const uint2* r0 = (const uint2*)(g_inp_h + (size_t)b0 * D_DIM);
        uint2 a0 = r0[lane +  0];
        uint2 a1 = r0[lane + 32];
        uint2 a2 = r0[lane + 64];
        uint2 a3 = r0[lane + 96];
        float acc0 = dot_w_h(w0, a0) + dot_w_h(w1, a1)
                   + dot_w_h(w2, a2) + dot_w_h(w3, a3);
        #pragma unroll
        for (int off = 16; off > 0; off >>= 1)
            acc0 += __shfl_xor_sync(0xFFFFFFFFu, acc0, off);
        if (lane == 0) out[e0] = acc0 + bv;
    }
}

// ---------------- fallback: direct gather (proven in round 2) ----------------
#define THREADS 256
#define WARPS (THREADS / 32)

__global__ __launch_bounds__(THREADS)
void sparse_proj_fallback(const float4* __restrict__ inp,
                          const void* __restrict__ indices,
                          const float4* __restrict__ weight,
                          const float* __restrict__ bias,
                          float* __restrict__ out,
                          long long vocab, int K)
{
    __shared__ float4 s_in[D4];
    const int b = blockIdx.x;
    const int tid = threadIdx.x;
    const int warp = tid >> 5;
    const int lane = tid & 31;
    const int is64 = g_idx_is64;
    const int k_per_warp = K / WARPS;

    if (tid < D4) s_in[tid] = inp[(size_t)b * D4 + tid];
    __syncthreads();

    float4 iv0 = s_in[lane +  0];
    float4 iv1 = s_in[lane + 32];
    float4 iv2 = s_in[lane + 64];
    float4 iv3 = s_in[lane + 96];

    const size_t idx_base = (size_t)b * K + (size_t)warp * k_per_warp;
    float* out_row = out + idx_base;

    for (int kk = 0; kk < k_per_warp; kk++) {
        long long r0 = load_index(indices, idx_base + kk, is64, vocab);
        const float4* w0 = weight + r0 * D4;
        float4 a0 = w0[lane +  0];
        float4 a1 = w0[lane + 32];
        float4 a2 = w0[lane + 64];
        float4 a3 = w0[lane + 96];
        float acc0 = a0.x * iv0.x + a0.y * iv0.y + a0.z * iv0.z + a0.w * iv0.w
                   + a1.x * iv1.x + a1.y * iv1.y + a1.z * iv1.z + a1.w * iv1.w
                   + a2.x * iv2.x + a2.y * iv2.y + a2.z * iv2.z + a2.w * iv2.w
                   + a3.x * iv3.x + a3.y * iv3.y + a3.z * iv3.z + a3.w * iv3.w;
        #pragma unroll
        for (int off = 16; off > 0; off >>= 1)
            acc0 += __shfl_xor_sync(0xFFFFFFFFu, acc0, off);
        if (lane == 0) out_row[kk] = acc0 + __ldg(bias + r0);
    }
}

extern "C" void kernel_launch(void* const* d_in, const int* in_sizes, int n_in,
                              void* d_out, int out_size)
{
    const float4* inp     = (const float4*)d_in[0];
    const void*   indices = d_in[1];
    const float4* weight  = (const float4*)d_in[3];
    const float*  bias    = (const float*)d_in[4];
    float*        out     = (float*)d_out;

    const long long V  = (long long)in_sizes[4];
    const int       D  = (int)((long long)in_sizes[3] / V);
    const int       B  = in_sizes[0] / D;
    const int       K  = in_sizes[1] / B;
    const int       BK = in_sizes[1];

    probe_idx_dtype<<<1, 1>>>((const long long*)indices, BK, V);

    const bool csr_ok = (D == D_DIM) && (V <= V_FIXED) && (BK <= BK_FIXED) &&
                        ((long long)B * D <= (long long)B_FIXED * D_DIM) &&
                        (K % 1 == 0);

    if (csr_ok) {
        const int Vi = (int)V;
        const int n4 = B * D / 4;
        const int nblk_scan = (Vi + SCAN_BLK - 1) / SCAN_BLK;

        convert_inp_fp16<<<(n4 + 255) / 256, 256>>>(inp, n4);
        zero_counts<<<(Vi + 255) / 256, 256>>>(Vi);
        histogram_idx<<<(BK + 255) / 256, 256>>>(indices, BK, V);
        scan_blocks<<<nblk_scan, SCAN_BLK>>>(Vi);
        scan_partials<<<1, 1>>>(nblk_scan);
        add_partials<<<nblk_scan, SCAN_BLK>>>(Vi);
        scatter_entries<<<(BK + 255) / 256, 256>>>(indices, BK, V);
        csr_main<<<(Vi + 7) / 8, 256>>>(weight, bias, out, Vi, BK, K);
    } else {
        sparse_proj_fallback<<<B, THREADS>>>(inp, indices, weight, bias, out, V, K);
    }
}

// round 4
// speedup vs baseline: 1.6863x; 1.0405x over previous
#include <cuda_runtime.h>
#include <cuda_fp16.h>
#include <cstdint>

// SparseProjection: out[b,k] = dot(weight[indices[b,k]], inp[b]) + bias[indices[b,k]]
// B=4096, K=128, D=512, V=128000.
// Strategy: bucket entries by vocab index (fixed-capacity buckets, no scan);
// one warp per vocab row reads weight[v] ONCE (sequential stream) and loops
// over its ~4 entries, reading inp[b] from an fp16 copy (4MB, L2-resident).

#define D_DIM 512
#define D4 (D_DIM / 4)
#define B_FIXED 4096
#define V_FIXED 128000
#define BK_FIXED (B_FIXED * 128)
#define CAP 32            // bucket capacity; Poisson(4.1) P(>32) ~ 1e-20
#define OVF_CAP 65536

// ---- static device scratch (no allocation allowed) ----
__device__ int    g_idx_is64;
__device__ int    g_counts[V_FIXED];
__device__ int    g_bucket[(size_t)V_FIXED * CAP];   // 16 MB
__device__ int    g_overflow[OVF_CAP];
__device__ int    g_overflow_n;
__device__ __half g_inp_h[B_FIXED * D_DIM];          // 4 MB fp16 copy of inp

// ---------------- dtype probe (indices may be int32 or int64) --------------
__global__ void probe_idx_dtype(const long long* __restrict__ idx64,
                                long long n_elems, long long vocab)
{
    int ok = 1;
    long long n = n_elems < 256 ? n_elems : 256;
    for (long long i = 0; i < n; i++) {
        long long v = idx64[i];
        if (v < 0 || v >= vocab) { ok = 0; break; }
    }
    g_idx_is64 = ok;
}

__device__ __forceinline__ long long load_index(const void* idx, size_t i,
                                                int is64, long long vocab)
{
    long long v = is64 ? ((const long long*)idx)[i]
                       : (long long)((const int*)idx)[i];
    v = v < 0 ? 0 : v;
    v = v >= vocab ? vocab - 1 : v;
    return v;
}

// ---------------- fused prep: zero counts + fp32->fp16 convert -------------
__global__ void prep_fused(const float4* __restrict__ inp, int n4, int V)
{
    int i = blockIdx.x * blockDim.x + threadIdx.x;
    int stride = gridDim.x * blockDim.x;
    if (i == 0) g_overflow_n = 0;
    for (int j = i; j < V; j += stride) g_counts[j] = 0;
    for (int j = i; j < n4; j += stride) {
        float4 f = inp[j];
        __half2 lo = __floats2half2_rn(f.x, f.y);
        __half2 hi = __floats2half2_rn(f.z, f.w);
        uint2 p;
        p.x = *(const unsigned int*)&lo;
        p.y = *(const unsigned int*)&hi;
        ((uint2*)g_inp_h)[j] = p;
    }
}

// ---------------- bucket scatter (no histogram / scan needed) --------------
__global__ void scatter_bucket(const void* __restrict__ idx, int BK, long long vocab)
{
    int e = blockIdx.x * blockDim.x + threadIdx.x;
    if (e < BK) {
        int v = (int)load_index(idx, (size_t)e, g_idx_is64, vocab);
        int pos = atomicAdd(&g_counts[v], 1);
        if (pos < CAP) {
            g_bucket[(size_t)v * CAP + pos] = e;
        } else {
            int o = atomicAdd(&g_overflow_n, 1);
            if (o < OVF_CAP) g_overflow[o] = e;
        }
    }
}

// ---------------- main kernel: one warp per vocab row ----------------------
__device__ __forceinline__ float dot_w_h(float4 w, uint2 p)
{
    float2 lo = __half22float2(*(const __half2*)&p.x);
    float2 hi = __half22float2(*(const __half2*)&p.y);
    return w.x * lo.x + w.y * lo.y + w.z * hi.x + w.w * hi.y;
}

__global__ __launch_bounds__(256)
void csr_main(const float4* __restrict__ weight,
              const float*  __restrict__ bias,
              float* __restrict__ out,
              int V, int K)
{
    const int warp = threadIdx.x >> 5;
    const int lane = threadIdx.x & 31;
    const int v = blockIdx.x * 8 + warp;
    if (v >= V) return;

    int cnt = g_counts[v];
    if (cnt <= 0) return;
    if (cnt > CAP) cnt = CAP;      // overflow handled separately

    const float4* wr = weight + (size_t)v * D4;
    float4 w0 = wr[lane +  0];
    float4 w1 = wr[lane + 32];
    float4 w2 = wr[lane + 64];
    float4 w3 = wr[lane + 96];
    const float bv = __ldg(bias + v);
    const int* bkt = g_bucket + (size_t)v * CAP;

    int i = 0;
    for (; i + 2 <= cnt; i += 2) {
        int e0 = bkt[i];
        int e1 = bkt[i + 1];
        int b0 = e0 / K;
        int b1 = e1 / K;
        const uint2* r0 = (const uint2*)(g_inp_h + (size_t)b0 * D_DIM);
        const uint2* r1 = (const uint2*)(g_inp_h + (size_t)b1 * D_DIM);
        uint2 a0 = r0[lane +  0];
        uint2 a1 = r0[lane + 32];
        uint2 a2 = r0[lane + 64];
        uint2 a3 = r0[lane + 96];
        uint2 c0 = r1[lane +  0];
        uint2 c1 = r1[lane + 32];
        uint2 c2 = r1[lane + 64];
        uint2 c3 = r1[lane + 96];

        float acc0 = dot_w_h(w0, a0) + dot_w_h(w1, a1)
                   + dot_w_h(w2, a2) + dot_w_h(w3, a3);
        float acc1 = dot_w_h(w0, c0) + dot_w_h(w1, c1)
                   + dot_w_h(w2, c2) + dot_w_h(w3, c3);

        #pragma unroll
        for (int off = 16; off > 0; off >>= 1) {
            acc0 += __shfl_xor_sync(0xFFFFFFFFu, acc0, off);
            acc1 += __shfl_xor_sync(0xFFFFFFFFu, acc1, off);
        }
        if (lane == 0) {
            out[e0] = acc0 + bv;
            out[e1] = acc1 + bv;
        }
    }
    if (i < cnt) {
        int e0 = bkt[i];
        int b0 = e0 / K;
        const uint2* r0 = (const uint2*)(g_inp_h + (size_t)b0 * D_DIM);
        uint2 a0 = r0[lane +  0];
        uint2 a1 = r0[lane + 32];
        uint2 a2 = r0[lane + 64];
        uint2 a3 = r0[lane + 96];
        float acc0 = dot_w_h(w0, a0) + dot_w_h(w1, a1)
                   + dot_w_h(w2, a2) + dot_w_h(w3, a3);
        #pragma unroll
        for (int off = 16; off > 0; off >>= 1)
            acc0 += __shfl_xor_sync(0xFFFFFFFFu, acc0, off);
        if (lane == 0) out[e0] = acc0 + bv;
    }
}

// ---------------- overflow fixup (expected empty; fixed grid) --------------
__global__ void overflow_fix(const void* __restrict__ idx,
                             const float4* __restrict__ weight,
                             const float*  __restrict__ bias,
                             float* __restrict__ out,
                             int K, long long vocab)
{
    int n = g_overflow_n;
    if (n > OVF_CAP) n = OVF_CAP;
    if (n == 0) return;
    const int lane = threadIdx.x & 31;
    const int warps_per_blk = blockDim.x >> 5;
    const int is64 = g_idx_is64;

    for (int i = blockIdx.x * warps_per_blk + (threadIdx.x >> 5);
         i < n; i += gridDim.x * warps_per_blk) {
        int e = g_overflow[i];
        int b = e / K;
        long long v = load_index(idx, (size_t)e, is64, vocab);
        const float4* wr = weight + v * D4;
        const uint2* r0 = (const uint2*)(g_inp_h + (size_t)b * D_DIM);
        float acc = dot_w_h(wr[lane +  0], r0[lane +  0])
                  + dot_w_h(wr[lane + 32], r0[lane + 32])
                  + dot_w_h(wr[lane + 64], r0[lane + 64])
                  + dot_w_h(wr[lane + 96], r0[lane + 96]);
        #pragma unroll
        for (int off = 16; off > 0; off >>= 1)
            acc += __shfl_xor_sync(0xFFFFFFFFu, acc, off);
        if (lane == 0) out[e] = acc + __ldg(bias + v);
    }
}

// ---------------- fallback: direct gather (proven round 2) -----------------
#define THREADS 256
#define WARPS (THREADS / 32)

__global__ __launch_bounds__(THREADS)
void sparse_proj_fallback(const float4* __restrict__ inp,
                          const void* __restrict__ indices,
                          const float4* __restrict__ weight,
                          const float* __restrict__ bias,
                          float* __restrict__ out,
                          long long vocab, int K)
{
    __shared__ float4 s_in[D4];
    const int b = blockIdx.x;
    const int tid = threadIdx.x;
    const int warp = tid >> 5;
    const int lane = tid & 31;
    const int is64 = g_idx_is64;
    const int k_per_warp = K / WARPS;

    if (tid < D4) s_in[tid] = inp[(size_t)b * D4 + tid];
    __syncthreads();

    float4 iv0 = s_in[lane +  0];
    float4 iv1 = s_in[lane + 32];
    float4 iv2 = s_in[lane + 64];
    float4 iv3 = s_in[lane + 96];

    const size_t idx_base = (size_t)b * K + (size_t)warp * k_per_warp;
    float* out_row = out + idx_base;

    for (int kk = 0; kk < k_per_warp; kk++) {
        long long r0 = load_index(indices, idx_base + kk, is64, vocab);
        const float4* w0 = weight + r0 * D4;
        float4 a0 = w0[lane +  0];
        float4 a1 = w0[lane + 32];
        float4 a2 = w0[lane + 64];
        float4 a3 = w0[lane + 96];
        float acc0 = a0.x * iv0.x + a0.y * iv0.y + a0.z * iv0.z + a0.w * iv0.w
                   + a1.x * iv1.x + a1.y * iv1.y + a1.z * iv1.z + a1.w * iv1.w
                   + a2.x * iv2.x + a2.y * iv2.y + a2.z * iv2.z + a2.w * iv2.w
                   + a3.x * iv3.x + a3.y * iv3.y + a3.z * iv3.z + a3.w * iv3.w;
        #pragma unroll
        for (int off = 16; off > 0; off >>= 1)
            acc0 += __shfl_xor_sync(0xFFFFFFFFu, acc0, off);
        if (lane == 0) out_row[kk] = acc0 + __ldg(bias + r0);
    }
}

extern "C" void kernel_launch(void* const* d_in, const int* in_sizes, int n_in,
                              void* d_out, int out_size)
{
    const float4* inp     = (const float4*)d_in[0];
    const void*   indices = d_in[1];
    const float4* weight  = (const float4*)d_in[3];
    const float*  bias    = (const float*)d_in[4];
    float*        out     = (float*)d_out;

    const long long V  = (long long)in_sizes[4];
    const int       D  = (int)((long long)in_sizes[3] / V);
    const int       B  = in_sizes[0] / D;
    const int       K  = in_sizes[1] / B;
    const int       BK = in_sizes[1];

    probe_idx_dtype<<<1, 1>>>((const long long*)indices, BK, V);

    const bool csr_ok = (D == D_DIM) && (V <= V_FIXED) && (BK <= BK_FIXED) &&
                        ((long long)B * D <= (long long)B_FIXED * D_DIM);

    if (csr_ok) {
        const int Vi = (int)V;
        const int n4 = B * D / 4;

        prep_fused<<<1024, 256>>>(inp, n4, Vi);
        scatter_bucket<<<(BK + 255) / 256, 256>>>(indices, BK, V);
        csr_main<<<(Vi + 7) / 8, 256>>>(weight, bias, out, Vi, K);
        overflow_fix<<<128, 256>>>(indices, weight, bias, out, K, V);
    } else {
        sparse_proj_fallback<<<B, THREADS>>>(inp, indices, weight, bias, out, V, K);
    }
}

// round 5
// speedup vs baseline: 2.1445x; 1.2717x over previous
#include <cuda_runtime.h>
#include <cuda_fp16.h>
#include <cstdint>

// SparseProjection: out[b,k] = dot(weight[indices[b,k]], inp[b]) + bias[indices[b,k]]
// B=4096, K=128, D=512, V=128000.
// Strategy: bucket entries by vocab index; one warp per vocab row converts
// weight[v] to half2 regs ONCE, then runs HFMA2 dots against the fp16 copy of
// inp (4MB, L2-resident). Weight is a single sequential 262MB DRAM stream.

#define D_DIM 512
#define D4 (D_DIM / 4)
#define B_FIXED 4096
#define V_FIXED 128000
#define BK_FIXED (B_FIXED * 128)
#define CAP 32            // bucket capacity; Poisson(4.1) P(>32) ~ 1e-20
#define OVF_CAP 65536
#define OVF_BLOCKS 16

// ---- static device scratch (no allocation allowed) ----
__device__ int    g_idx_is64;
__device__ int    g_counts[V_FIXED];
__device__ int    g_bucket[(size_t)V_FIXED * CAP];   // 16 MB
__device__ int    g_overflow[OVF_CAP];
__device__ int    g_overflow_n;
__device__ __half g_inp_h[B_FIXED * D_DIM];          // 4 MB fp16 copy of inp

// ---------------- dtype probe (indices may be int32 or int64) --------------
__global__ void probe_idx_dtype(const long long* __restrict__ idx64,
                                long long n_elems, long long vocab)
{
    const int lane = threadIdx.x;
    int ok = 1;
    long long n = n_elems < 256 ? n_elems : 256;
    for (long long i = lane; i < n; i += 32) {
        long long v = idx64[i];
        if (v < 0 || v >= vocab) ok = 0;
    }
    ok = __all_sync(0xFFFFFFFFu, ok);
    if (lane == 0) g_idx_is64 = ok;
}

__device__ __forceinline__ long long load_index(const void* idx, size_t i,
                                                int is64, long long vocab)
{
    long long v = is64 ? ((const long long*)idx)[i]
                       : (long long)((const int*)idx)[i];
    v = v < 0 ? 0 : v;
    v = v >= vocab ? vocab - 1 : v;
    return v;
}

// ---------------- fused prep: zero counts + fp32->fp16 convert -------------
__global__ void prep_fused(const float4* __restrict__ inp, int n4, int V)
{
    int i = blockIdx.x * blockDim.x + threadIdx.x;
    int stride = gridDim.x * blockDim.x;
    if (i == 0) g_overflow_n = 0;
    for (int j = i; j < V; j += stride) g_counts[j] = 0;
    for (int j = i; j < n4; j += stride) {
        float4 f = inp[j];
        __half2 lo = __floats2half2_rn(f.x, f.y);
        __half2 hi = __floats2half2_rn(f.z, f.w);
        uint2 p;
        p.x = *(const unsigned int*)&lo;
        p.y = *(const unsigned int*)&hi;
        ((uint2*)g_inp_h)[j] = p;
    }
}

// ---------------- bucket scatter (no histogram / scan needed) --------------
__global__ void scatter_bucket(const void* __restrict__ idx, int BK, long long vocab)
{
    int e = blockIdx.x * blockDim.x + threadIdx.x;
    if (e < BK) {
        int v = (int)load_index(idx, (size_t)e, g_idx_is64, vocab);
        int pos = atomicAdd(&g_counts[v], 1);
        if (pos < CAP) {
            g_bucket[(size_t)v * CAP + pos] = e;
        } else {
            int o = atomicAdd(&g_overflow_n, 1);
            if (o < OVF_CAP) g_overflow[o] = e;
        }
    }
}

// ---------------- helpers ----------------
__device__ __forceinline__ float dot_w_h(float4 w, uint2 p)
{
    float2 lo = __half22float2(*(const __half2*)&p.x);
    float2 hi = __half22float2(*(const __half2*)&p.y);
    return w.x * lo.x + w.y * lo.y + w.z * hi.x + w.w * hi.y;
}

// half2 dot of 8 pairs: two chains of 4, combine, promote to fp32.
__device__ __forceinline__ float dot8_h2(const __half2* w, uint2 a, uint2 b,
                                         uint2 c, uint2 d)
{
    const __half2* x0 = (const __half2*)&a.x;  // a.x, a.y
    const __half2* x1 = (const __half2*)&c.x;
    __half2 s0 = __hmul2(w[0], x0[0]);
    s0 = __hfma2(w[1], x0[1], s0);
    const __half2* xb = (const __half2*)&b.x;
    s0 = __hfma2(w[2], xb[0], s0);
    s0 = __hfma2(w[3], xb[1], s0);
    __half2 s1 = __hmul2(w[4], x1[0]);
    s1 = __hfma2(w[5], x1[1], s1);
    const __half2* xd = (const __half2*)&d.x;
    s1 = __hfma2(w[6], xd[0], s1);
    s1 = __hfma2(w[7], xd[1], s1);
    float2 f = __half22float2(__hadd2(s0, s1));
    return f.x + f.y;
}

// ---------------- main kernel: one warp per vocab row + overflow tail ------
__global__ __launch_bounds__(128)
void csr_main(const float4* __restrict__ weight,
              const float*  __restrict__ bias,
              float* __restrict__ out,
              int V, int K, int kshift, int rowBlocks,
              const void* __restrict__ idx, long long vocab)
{
    const int warp = threadIdx.x >> 5;
    const int lane = threadIdx.x & 31;

    if (blockIdx.x >= rowBlocks) {
        // ---- overflow fixup (expected empty) ----
        int n = g_overflow_n;
        if (n > OVF_CAP) n = OVF_CAP;
        if (n == 0) return;
        const int is64 = g_idx_is64;
        const int wpb = blockDim.x >> 5;
        for (int i = (blockIdx.x - rowBlocks) * wpb + warp;
             i < n; i += OVF_BLOCKS * wpb) {
            int e = g_overflow[i];
            int b = e / K;
            long long v = load_index(idx, (size_t)e, is64, vocab);
            const float4* wr = weight + v * D4;
            const uint2* r0 = (const uint2*)(g_inp_h + (size_t)b * D_DIM);
            float acc = dot_w_h(wr[lane +  0], r0[lane +  0])
                      + dot_w_h(wr[lane + 32], r0[lane + 32])
                      + dot_w_h(wr[lane + 64], r0[lane + 64])
                      + dot_w_h(wr[lane + 96], r0[lane + 96]);
            #pragma unroll
            for (int off = 16; off > 0; off >>= 1)
                acc += __shfl_xor_sync(0xFFFFFFFFu, acc, off);
            if (lane == 0) out[e] = acc + __ldg(bias + v);
        }
        return;
    }

    const int v = blockIdx.x * 4 + warp;
    if (v >= V) return;

    int cnt = g_counts[v];
    if (cnt <= 0) return;
    if (cnt > CAP) cnt = CAP;      // overflow handled by tail blocks

    // Load weight row (sequential DRAM stream), convert once to half2 regs.
    const float4* wr = weight + (size_t)v * D4;
    float4 wa = wr[lane +  0];
    float4 wb = wr[lane + 32];
    float4 wc = wr[lane + 64];
    float4 wd = wr[lane + 96];
    __half2 wh[8];
    wh[0] = __floats2half2_rn(wa.x, wa.y);
    wh[1] = __floats2half2_rn(wa.z, wa.w);
    wh[2] = __floats2half2_rn(wb.x, wb.y);
    wh[3] = __floats2half2_rn(wb.z, wb.w);
    wh[4] = __floats2half2_rn(wc.x, wc.y);
    wh[5] = __floats2half2_rn(wc.z, wc.w);
    wh[6] = __floats2half2_rn(wd.x, wd.y);
    wh[7] = __floats2half2_rn(wd.z, wd.w);
    const float bv = __ldg(bias + v);
    const int* bkt = g_bucket + (size_t)v * CAP;

    int i = 0;
    for (; i + 2 <= cnt; i += 2) {
        int e0 = bkt[i];
        int e1 = bkt[i + 1];
        int b0 = (kshift >= 0) ? (e0 >> kshift) : (e0 / K);
        int b1 = (kshift >= 0) ? (e1 >> kshift) : (e1 / K);
        const uint2* r0 = (const uint2*)(g_inp_h + (size_t)b0 * D_DIM);
        const uint2* r1 = (const uint2*)(g_inp_h + (size_t)b1 * D_DIM);
        uint2 a0 = r0[lane +  0];
        uint2 a1 = r0[lane + 32];
        uint2 a2 = r0[lane + 64];
        uint2 a3 = r0[lane + 96];
        uint2 c0 = r1[lane +  0];
        uint2 c1 = r1[lane + 32];
        uint2 c2 = r1[lane + 64];
        uint2 c3 = r1[lane + 96];

        float acc0 = dot8_h2(wh, a0, a1, a2, a3);
        float acc1 = dot8_h2(wh, c0, c1, c2, c3);

        #pragma unroll
        for (int off = 16; off > 0; off >>= 1) {
            acc0 += __shfl_xor_sync(0xFFFFFFFFu, acc0, off);
            acc1 += __shfl_xor_sync(0xFFFFFFFFu, acc1, off);
        }
        if (lane == 0) {
            out[e0] = acc0 + bv;
            out[e1] = acc1 + bv;
        }
    }
    if (i < cnt) {
        int e0 = bkt[i];
        int b0 = (kshift >= 0) ? (e0 >> kshift) : (e0 / K);
        const uint2* r0 = (const uint2*)(g_inp_h + (size_t)b0 * D_DIM);
        uint2 a0 = r0[lane +  0];
        uint2 a1 = r0[lane + 32];
        uint2 a2 = r0[lane + 64];
        uint2 a3 = r0[lane + 96];
        float acc0 = dot8_h2(wh, a0, a1, a2, a3);
        #pragma unroll
        for (int off = 16; off > 0; off >>= 1)
            acc0 += __shfl_xor_sync(0xFFFFFFFFu, acc0, off);
        if (lane == 0) out[e0] = acc0 + bv;
    }
}

// ---------------- fallback: direct gather (proven round 2) -----------------
#define THREADS 256
#define WARPS (THREADS / 32)

__global__ __launch_bounds__(THREADS)
void sparse_proj_fallback(const float4* __restrict__ inp,
                          const void* __restrict__ indices,
                          const float4* __restrict__ weight,
                          const float* __restrict__ bias,
                          float* __restrict__ out,
                          long long vocab, int K)
{
    __shared__ float4 s_in[D4];
    const int b = blockIdx.x;
    const int tid = threadIdx.x;
    const int warp = tid >> 5;
    const int lane = tid & 31;
    const int is64 = g_idx_is64;
    const int k_per_warp = K / WARPS;

    if (tid < D4) s_in[tid] = inp[(size_t)b * D4 + tid];
    __syncthreads();

    float4 iv0 = s_in[lane +  0];
    float4 iv1 = s_in[lane + 32];
    float4 iv2 = s_in[lane + 64];
    float4 iv3 = s_in[lane + 96];

    const size_t idx_base = (size_t)b * K + (size_t)warp * k_per_warp;
    float* out_row = out + idx_base;

    for (int kk = 0; kk < k_per_warp; kk++) {
        long long r0 = load_index(indices, idx_base + kk, is64, vocab);
        const float4* w0 = weight + r0 * D4;
        float4 a0 = w0[lane +  0];
        float4 a1 = w0[lane + 32];
        float4 a2 = w0[lane + 64];
        float4 a3 = w0[lane + 96];
        float acc0 = a0.x * iv0.x + a0.y * iv0.y + a0.z * iv0.z + a0.w * iv0.w
                   + a1.x * iv1.x + a1.y * iv1.y + a1.z * iv1.z + a1.w * iv1.w
                   + a2.x * iv2.x + a2.y * iv2.y + a2.z * iv2.z + a2.w * iv2.w
                   + a3.x * iv3.x + a3.y * iv3.y + a3.z * iv3.z + a3.w * iv3.w;
        #pragma unroll
        for (int off = 16; off > 0; off >>= 1)
            acc0 += __shfl_xor_sync(0xFFFFFFFFu, acc0, off);
        if (lane == 0) out_row[kk] = acc0 + __ldg(bias + r0);
    }
}

extern "C" void kernel_launch(void* const* d_in, const int* in_sizes, int n_in,
                              void* d_out, int out_size)
{
    const float4* inp     = (const float4*)d_in[0];
    const void*   indices = d_in[1];
    const float4* weight  = (const float4*)d_in[3];
    const float*  bias    = (const float*)d_in[4];
    float*        out     = (float*)d_out;

    const long long V  = (long long)in_sizes[4];
    const int       D  = (int)((long long)in_sizes[3] / V);
    const int       B  = in_sizes[0] / D;
    const int       K  = in_sizes[1] / B;
    const int       BK = in_sizes[1];

    probe_idx_dtype<<<1, 32>>>((const long long*)indices, BK, V);

    const bool csr_ok = (D == D_DIM) && (V <= V_FIXED) && (BK <= BK_FIXED) &&
                        ((long long)B * D <= (long long)B_FIXED * D_DIM);

    if (csr_ok) {
        const int Vi = (int)V;
        const int n4 = B * D / 4;
        const int rowBlocks = (Vi + 3) / 4;

        int kshift = -1;
        if ((K & (K - 1)) == 0) {
            kshift = 0;
            while ((1 << kshift) < K) kshift++;
        }

        prep_fused<<<1024, 256>>>(inp, n4, Vi);
        scatter_bucket<<<(BK + 255) / 256, 256>>>(indices, BK, V);
        csr_main<<<rowBlocks + OVF_BLOCKS, 128>>>(weight, bias, out,
                                                  Vi, K, kshift, rowBlocks,
                                                  indices, V);
    } else {
        sparse_proj_fallback<<<B, THREADS>>>(inp, indices, weight, bias, out, V, K);
    }
}

// round 6
// speedup vs baseline: 2.3172x; 1.0805x over previous
#include <cuda_runtime.h>
#include <cuda_fp16.h>
#include <cstdint>

// SparseProjection: out[b,k] = dot(weight[indices[b,k]], inp[b]) + bias[indices[b,k]]
// B=4096, K=128, D=512, V=128000.
// Strategy: bucket entries by vocab index; one warp per vocab row converts
// weight[v] to half2 regs ONCE (streaming loads), then HFMA2 dots against an
// fp16 copy of inp (4MB, L2-resident) with 4-entry ILP / LDG.128 gathers.

#define D_DIM 512
#define D4 (D_DIM / 4)
#define B_FIXED 4096
#define V_FIXED 128000
#define BK_FIXED (B_FIXED * 128)
#define CAP 32            // bucket capacity; Poisson(4.1) P(>32) ~ 1e-20
#define OVF_CAP 65536
#define OVF_BLOCKS 16

// ---- static device scratch (no allocation allowed) ----
__device__ int    g_idx_is64;
__device__ int    g_counts[V_FIXED];
__device__ int    g_bucket[(size_t)V_FIXED * CAP];   // 16 MB
__device__ int    g_overflow[OVF_CAP];
__device__ int    g_overflow_n;
__device__ __half g_inp_h[B_FIXED * D_DIM];          // 4 MB fp16 copy of inp

__device__ __forceinline__ long long load_index(const void* idx, size_t i,
                                                int is64, long long vocab)
{
    long long v = is64 ? ((const long long*)idx)[i]
                       : (long long)((const int*)idx)[i];
    v = v < 0 ? 0 : v;
    v = v >= vocab ? vocab - 1 : v;
    return v;
}

// ------ fused prep: dtype probe + zero counts + fp32->fp16 convert ---------
__global__ void prep_fused(const float4* __restrict__ inp, int n4, int V,
                           const long long* __restrict__ idx64,
                           long long n_elems, long long vocab)
{
    int i = blockIdx.x * blockDim.x + threadIdx.x;
    int stride = gridDim.x * blockDim.x;

    if (blockIdx.x == 0 && threadIdx.x < 32) {
        // dtype probe: int32 data viewed as int64 has garbage high words.
        const int lane = threadIdx.x;
        int ok = 1;
        long long n = n_elems < 256 ? n_elems : 256;
        for (long long j = lane; j < n; j += 32) {
            long long v = idx64[j];
            if (v < 0 || v >= vocab) ok = 0;
        }
        ok = __all_sync(0xFFFFFFFFu, ok);
        if (lane == 0) { g_idx_is64 = ok; g_overflow_n = 0; }
    }

    for (int j = i; j < V; j += stride) g_counts[j] = 0;
    for (int j = i; j < n4; j += stride) {
        float4 f = inp[j];
        __half2 lo = __floats2half2_rn(f.x, f.y);
        __half2 hi = __floats2half2_rn(f.z, f.w);
        uint2 p;
        p.x = *(const unsigned int*)&lo;
        p.y = *(const unsigned int*)&hi;
        ((uint2*)g_inp_h)[j] = p;
    }
}

// ---------------- bucket scatter (no histogram / scan needed) --------------
__global__ void scatter_bucket(const void* __restrict__ idx, int BK, long long vocab)
{
    int e = blockIdx.x * blockDim.x + threadIdx.x;
    if (e < BK) {
        int v = (int)load_index(idx, (size_t)e, g_idx_is64, vocab);
        int pos = atomicAdd(&g_counts[v], 1);
        if (pos < CAP) {
            g_bucket[(size_t)v * CAP + pos] = e;
        } else {
            int o = atomicAdd(&g_overflow_n, 1);
            if (o < OVF_CAP) g_overflow[o] = e;
        }
    }
}

// ---------------- helpers ----------------
__device__ __forceinline__ float dot_w_h(float4 w, uint2 p)
{
    float2 lo = __half22float2(*(const __half2*)&p.x);
    float2 hi = __half22float2(*(const __half2*)&p.y);
    return w.x * lo.x + w.y * lo.y + w.z * hi.x + w.w * hi.y;
}

// Dot of 16 halves (two uint4 = two 8-half groups) against 8 half2 weights.
__device__ __forceinline__ float dot16_h2(const __half2* w, uint4 q0, uint4 q1)
{
    const __half2* h0 = (const __half2*)&q0;
    const __half2* h1 = (const __half2*)&q1;
    __half2 s0 = __hmul2(w[0], h0[0]);
    s0 = __hfma2(w[1], h0[1], s0);
    s0 = __hfma2(w[2], h0[2], s0);
    s0 = __hfma2(w[3], h0[3], s0);
    __half2 s1 = __hmul2(w[4], h1[0]);
    s1 = __hfma2(w[5], h1[1], s1);
    s1 = __hfma2(w[6], h1[2], s1);
    s1 = __hfma2(w[7], h1[3], s1);
    float2 f = __half22float2(__hadd2(s0, s1));
    return f.x + f.y;
}

// ---------------- main kernel: one warp per vocab row + overflow tail ------
__global__ __launch_bounds__(128)
void csr_main(const float4* __restrict__ weight,
              const float*  __restrict__ bias,
              float* __restrict__ out,
              int V, int K, int kshift, int rowBlocks,
              const void* __restrict__ idx, long long vocab)
{
    const int warp = threadIdx.x >> 5;
    const int lane = threadIdx.x & 31;

    if (blockIdx.x >= rowBlocks) {
        // ---- overflow fixup (expected empty) ----
        int n = g_overflow_n;
        if (n > OVF_CAP) n = OVF_CAP;
        if (n == 0) return;
        const int is64 = g_idx_is64;
        const int wpb = blockDim.x >> 5;
        for (int i = (blockIdx.x - rowBlocks) * wpb + warp;
             i < n; i += OVF_BLOCKS * wpb) {
            int e = g_overflow[i];
            int b = e / K;
            long long v = load_index(idx, (size_t)e, is64, vocab);
            const float4* wr = weight + v * D4;
            const uint2* r0 = (const uint2*)(g_inp_h + (size_t)b * D_DIM);
            float acc = dot_w_h(wr[lane +  0], r0[lane +  0])
                      + dot_w_h(wr[lane + 32], r0[lane + 32])
                      + dot_w_h(wr[lane + 64], r0[lane + 64])
                      + dot_w_h(wr[lane + 96], r0[lane + 96]);
            #pragma unroll
            for (int off = 16; off > 0; off >>= 1)
                acc += __shfl_xor_sync(0xFFFFFFFFu, acc, off);
            if (lane == 0) out[e] = acc + __ldg(bias + v);
        }
        return;
    }

    const int v = blockIdx.x * 4 + warp;
    if (v >= V) return;

    int cnt = g_counts[v];
    if (cnt <= 0) return;
    if (cnt > CAP) cnt = CAP;      // overflow handled by tail blocks

    // Load weight row (sequential stream, evict-first) and convert once to
    // half2 regs. Lane L owns halves [8L, 8L+8) and [256+8L, 256+8L+8),
    // matching the uint4 inp-load layout below.
    const float4* wr = weight + (size_t)v * D4;
    float4 wa = __ldcs(wr + 2 * lane);
    float4 wb = __ldcs(wr + 2 * lane + 1);
    float4 wc = __ldcs(wr + 64 + 2 * lane);
    float4 wd = __ldcs(wr + 64 + 2 * lane + 1);
    __half2 wh[8];
    wh[0] = __floats2half2_rn(wa.x, wa.y);
    wh[1] = __floats2half2_rn(wa.z, wa.w);
    wh[2] = __floats2half2_rn(wb.x, wb.y);
    wh[3] = __floats2half2_rn(wb.z, wb.w);
    wh[4] = __floats2half2_rn(wc.x, wc.y);
    wh[5] = __floats2half2_rn(wc.z, wc.w);
    wh[6] = __floats2half2_rn(wd.x, wd.y);
    wh[7] = __floats2half2_rn(wd.z, wd.w);
    const float bv = __ldg(bias + v);
    const int* bkt = g_bucket + (size_t)v * CAP;

    int i = 0;
    // ---- 4-entry chunks: 8 independent LDG.128 per lane in flight ----
    for (; i + 4 <= cnt; i += 4) {
        int e0 = bkt[i + 0];
        int e1 = bkt[i + 1];
        int e2 = bkt[i + 2];
        int e3 = bkt[i + 3];
        int b0 = (kshift >= 0) ? (e0 >> kshift) : (e0 / K);
        int b1 = (kshift >= 0) ? (e1 >> kshift) : (e1 / K);
        int b2 = (kshift >= 0) ? (e2 >> kshift) : (e2 / K);
        int b3 = (kshift >= 0) ? (e3 >> kshift) : (e3 / K);
        const uint4* r0 = (const uint4*)(g_inp_h + (size_t)b0 * D_DIM);
        const uint4* r1 = (const uint4*)(g_inp_h + (size_t)b1 * D_DIM);
        const uint4* r2 = (const uint4*)(g_inp_h + (size_t)b2 * D_DIM);
        const uint4* r3 = (const uint4*)(g_inp_h + (size_t)b3 * D_DIM);
        uint4 q00 = r0[lane];
        uint4 q01 = r0[lane + 32];
        uint4 q10 = r1[lane];
        uint4 q11 = r1[lane + 32];
        uint4 q20 = r2[lane];
        uint4 q21 = r2[lane + 32];
        uint4 q30 = r3[lane];
        uint4 q31 = r3[lane + 32];

        float acc0 = dot16_h2(wh, q00, q01);
        float acc1 = dot16_h2(wh, q10, q11);
        float acc2 = dot16_h2(wh, q20, q21);
        float acc3 = dot16_h2(wh, q30, q31);

        #pragma unroll
        for (int off = 16; off > 0; off >>= 1) {
            acc0 += __shfl_xor_sync(0xFFFFFFFFu, acc0, off);
            acc1 += __shfl_xor_sync(0xFFFFFFFFu, acc1, off);
            acc2 += __shfl_xor_sync(0xFFFFFFFFu, acc2, off);
            acc3 += __shfl_xor_sync(0xFFFFFFFFu, acc3, off);
        }
        if (lane == 0) {
            out[e0] = acc0 + bv;
            out[e1] = acc1 + bv;
            out[e2] = acc2 + bv;
            out[e3] = acc3 + bv;
        }
    }
    // ---- 2-entry chunk ----
    if (i + 2 <= cnt) {
        int e0 = bkt[i + 0];
        int e1 = bkt[i + 1];
        int b0 = (kshift >= 0) ? (e0 >> kshift) : (e0 / K);
        int b1 = (kshift >= 0) ? (e1 >> kshift) : (e1 / K);
        const uint4* r0 = (const uint4*)(g_inp_h + (size_t)b0 * D_DIM);
        const uint4* r1 = (const uint4*)(g_inp_h + (size_t)b1 * D_DIM);
        uint4 q00 = r0[lane];
        uint4 q01 = r0[lane + 32];
        uint4 q10 = r1[lane];
        uint4 q11 = r1[lane + 32];
        float acc0 = dot16_h2(wh, q00, q01);
        float acc1 = dot16_h2(wh, q10, q11);
        #pragma unroll
        for (int off = 16; off > 0; off >>= 1) {
            acc0 += __shfl_xor_sync(0xFFFFFFFFu, acc0, off);
            acc1 += __shfl_xor_sync(0xFFFFFFFFu, acc1, off);
        }
        if (lane == 0) {
            out[e0] = acc0 + bv;
            out[e1] = acc1 + bv;
        }
        i += 2;
    }
    // ---- single entry ----
    if (i < cnt) {
        int e0 = bkt[i];
        int b0 = (kshift >= 0) ? (e0 >> kshift) : (e0 / K);
        const uint4* r0 = (const uint4*)(g_inp_h + (size_t)b0 * D_DIM);
        uint4 q00 = r0[lane];
        uint4 q01 = r0[lane + 32];
        float acc0 = dot16_h2(wh, q00, q01);
        #pragma unroll
        for (int off = 16; off > 0; off >>= 1)
            acc0 += __shfl_xor_sync(0xFFFFFFFFu, acc0, off);
        if (lane == 0) out[e0] = acc0 + bv;
    }
}

// ---------------- fallback: direct gather (proven round 2) -----------------
#define THREADS 256
#define WARPS (THREADS / 32)

__global__ __launch_bounds__(THREADS)
void sparse_proj_fallback(const float4* __restrict__ inp,
                          const void* __restrict__ indices,
                          const float4* __restrict__ weight,
                          const float* __restrict__ bias,
                          float* __restrict__ out,
                          long long vocab, int K)
{
    __shared__ float4 s_in[D4];
    const int b = blockIdx.x;
    const int tid = threadIdx.x;
    const int warp = tid >> 5;
    const int lane = tid & 31;
    const int is64 = g_idx_is64;
    const int k_per_warp = K / WARPS;

    if (tid < D4) s_in[tid] = inp[(size_t)b * D4 + tid];
    __syncthreads();

    float4 iv0 = s_in[lane +  0];
    float4 iv1 = s_in[lane + 32];
    float4 iv2 = s_in[lane + 64];
    float4 iv3 = s_in[lane + 96];

    const size_t idx_base = (size_t)b * K + (size_t)warp * k_per_warp;
    float* out_row = out + idx_base;

    for (int kk = 0; kk < k_per_warp; kk++) {
        long long r0 = load_index(indices, idx_base + kk, is64, vocab);
        const float4* w0 = weight + r0 * D4;
        float4 a0 = w0[lane +  0];
        float4 a1 = w0[lane + 32];
        float4 a2 = w0[lane + 64];
        float4 a3 = w0[lane + 96];
        float acc0 = a0.x * iv0.x + a0.y * iv0.y + a0.z * iv0.z + a0.w * iv0.w
                   + a1.x * iv1.x + a1.y * iv1.y + a1.z * iv1.z + a1.w * iv1.w
                   + a2.x * iv2.x + a2.y * iv2.y + a2.z * iv2.z + a2.w * iv2.w
                   + a3.x * iv3.x + a3.y * iv3.y + a3.z * iv3.z + a3.w * iv3.w;
        #pragma unroll
        for (int off = 16; off > 0; off >>= 1)
            acc0 += __shfl_xor_sync(0xFFFFFFFFu, acc0, off);
        if (lane == 0) out_row[kk] = acc0 + __ldg(bias + r0);
    }
}

extern "C" void kernel_launch(void* const* d_in, const int* in_sizes, int n_in,
                              void* d_out, int out_size)
{
    const float4* inp     = (const float4*)d_in[0];
    const void*   indices = d_in[1];
    const float4* weight  = (const float4*)d_in[3];
    const float*  bias    = (const float*)d_in[4];
    float*        out     = (float*)d_out;

    const long long V  = (long long)in_sizes[4];
    const int       D  = (int)((long long)in_sizes[3] / V);
    const int       B  = in_sizes[0] / D;
    const int       K  = in_sizes[1] / B;
    const int       BK = in_sizes[1];

    const bool csr_ok = (D == D_DIM) && (V <= V_FIXED) && (BK <= BK_FIXED) &&
                        ((long long)B * D <= (long long)B_FIXED * D_DIM);

    if (csr_ok) {
        const int Vi = (int)V;
        const int n4 = B * D / 4;
        const int rowBlocks = (Vi + 3) / 4;

        int kshift = -1;
        if ((K & (K - 1)) == 0) {
            kshift = 0;
            while ((1 << kshift) < K) kshift++;
        }

        prep_fused<<<1024, 256>>>(inp, n4, Vi,
                                  (const long long*)indices, BK, V);
        scatter_bucket<<<(BK + 255) / 256, 256>>>(indices, BK, V);
        csr_main<<<rowBlocks + OVF_BLOCKS, 128>>>(weight, bias, out,
                                                  Vi, K, kshift, rowBlocks,
                                                  indices, V);
    } else {
        // probe needed only for fallback path
        prep_fused<<<1, 32>>>(inp, 0, 0, (const long long*)indices, BK, V);
        sparse_proj_fallback<<<B, THREADS>>>(inp, indices, weight, bias, out, V, K);
    }
}